// round 16
// baseline (speedup 1.0000x reference)
#include <cuda_runtime.h>
#include <math.h>

#define NN 110
#define ALPHA 0.2f

typedef unsigned long long u64;

__device__ __forceinline__ u64 ffma2(u64 a, u64 b, u64 c) {
    u64 d; asm("fma.rn.f32x2 %0, %1, %2, %3;" : "=l"(d) : "l"(a), "l"(b), "l"(c)); return d;
}
__device__ __forceinline__ u64 splat2(float x) {
    u64 d; asm("mov.b64 %0, {%1, %1};" : "=l"(d) : "f"(x)); return d;
}
__device__ __forceinline__ float2 unpack2(u64 v) {
    float2 r; asm("mov.b64 {%0, %1}, %2;" : "=f"(r.x), "=f"(r.y) : "l"(v)); return r;
}
__device__ __forceinline__ float lrelu(float v) { return v > 0.f ? v : ALPHA * v; }
__device__ __forceinline__ float sigm(float v) { return 1.f / (1.f + __expf(-v)); }
__device__ __forceinline__ float warp_sum(float v) {
#pragma unroll
    for (int o = 16; o > 0; o >>= 1) v += __shfl_xor_sync(0xffffffffu, v, o);
    return v;
}
__device__ __forceinline__ float warp_max(float v) {
#pragma unroll
    for (int o = 16; o > 0; o >>= 1) v = fmaxf(v, __shfl_xor_sync(0xffffffffu, v, o));
    return v;
}

// ---- global scratch ----
#define BMAX 2048
__device__ float    g_sigM[12100];                 // sigmoid(M), batch-invariant
__device__ float    g_xmT[(size_t)BMAX * 12100];   // [b][i][n]
__device__ float    g_h1T[(size_t)BMAX * 13200];   // [b][k=h*24+f][n]
__device__ unsigned g_am[BMAX * 440];              // [b][n][4]

// ================= K0: sigmoid(M) once =================
__global__ __launch_bounds__(256)
void k_sigm(const float* __restrict__ M)
{
    int idx = blockIdx.x * 256 + threadIdx.x;
    if (idx < 12100) g_sigM[idx] = sigm(M[idx]);
}

// ================= K1: Xm transpose + adjacency masks (vectorized, 512 thr) =================
__global__ __launch_bounds__(512)
void k_prep(const float* __restrict__ X, const float* __restrict__ A)
{
    __shared__ __align__(16) float tile[110 * 111];
    const int b = blockIdx.x, tid = threadIdx.x, lane = tid & 31, wid = tid >> 5;
    const float* Xb = X + (size_t)b * 12100;
    const float* Ab = A + (size_t)b * 12100;

    {
        const float4* x4 = (const float4*)Xb;
        const float4* m4 = (const float4*)g_sigM;
        for (int q = tid; q < 3025; q += 512) {
            float4 xv = x4[q];
            float4 mv = m4[q];
            int idx = q * 4;
            int n = idx / NN, i = idx - n * NN;
            float vals[4] = { xv.x * mv.x, xv.y * mv.y, xv.z * mv.z, xv.w * mv.w };
#pragma unroll
            for (int j = 0; j < 4; j++) {
                tile[i * 111 + n] = vals[j];
                if (++i == NN) { i = 0; n++; }
            }
        }
    }
    for (int w = wid; w < 440; w += 16) {
        int n = w >> 2, seg = w & 3;
        int m = seg * 32 + lane;
        float a = (m < NN) ? Ab[n * NN + m] : 0.f;
        unsigned bal = __ballot_sync(0xffffffffu, a > 0.f);
        if (lane == 0) g_am[b * 440 + w] = bal;
    }
    __syncthreads();
    {
        float4* d4 = (float4*)(g_xmT + (size_t)b * 12100);
        for (int q = tid; q < 3025; q += 512) {
            int idx = q * 4;
            int i = idx / NN, n = idx - i * NN;
            float4 o;
            float vals[4];
#pragma unroll
            for (int j = 0; j < 4; j++) {
                vals[j] = tile[i * 111 + n];
                if (++n == NN) { n = 0; i++; }
            }
            o.x = vals[0]; o.y = vals[1]; o.z = vals[2]; o.w = vals[3];
            d4[q] = o;
        }
    }
}

// ====== K2: layer-1, 256 threads, column-halved, cp.async-pipelined K-chunks ======
#define CHUNK 10
#define NCH 11
#define XBS 1120            // CHUNK * 112 floats per buffer
__global__ __launch_bounds__(256, 5)
void k_layer1(const float* __restrict__ W1, const float* __restrict__ as1,
              const float* __restrict__ an1, const float* __restrict__ b1)
{
    __shared__ __align__(16) float w1s[2640];
    __shared__ __align__(16) float fs[110 * 26 + 4];
    __shared__ __align__(16) float xbuf[2 * XBS];   // double-buffered Xm chunks [i_local][112]
    __shared__ float pes[220], pen[220];
    __shared__ float ess[112], ens[112];
    __shared__ unsigned ams[440];
    const int h = blockIdx.x, b = blockIdx.y, tid = threadIdx.x;

    const float* wsrc = W1 + h * 2640;
    for (int idx = tid; idx < 2640; idx += 256) w1s[idx] = wsrc[idx];
    for (int idx = tid; idx < 440; idx += 256) ams[idx] = g_am[b * 440 + idx];

    const unsigned xbuf_u32 = (unsigned)__cvta_generic_to_shared(xbuf);
    const float* xsrc = g_xmT + (size_t)b * 12100;

    // async loader: chunk c (rows c*10..c*10+9) into buffer par
    auto load_chunk = [&](int c, int par) {
        const unsigned dst0 = xbuf_u32 + (unsigned)(par * XBS * 4);
        const float* src0 = xsrc + c * CHUNK * NN;
        for (int idx = tid; idx < 550; idx += 256) {
            int r = idx / 55, q = idx - r * 55;
            unsigned d = dst0 + (unsigned)((r * 112 + q * 2) * 4);
            const float* s = src0 + r * NN + q * 2;
            asm volatile("cp.async.ca.shared.global [%0], [%1], 8;" :: "r"(d), "l"(s));
        }
        asm volatile("cp.async.commit_group;" ::: "memory");
    };

    const int half = tid / NN;               // 0 or 1 for tid<220
    const int n = tid - half * NN;
    const int c0 = half * 12;

    u64 acc[6];
#pragma unroll
    for (int j = 0; j < 6; j++) acc[j] = 0ull;

    load_chunk(0, 0);

    // --- stage A: pipelined GEMM over 11 K-chunks ---
    for (int c = 0; c < NCH; c++) {
        if (c + 1 < NCH) {
            load_chunk(c + 1, (c + 1) & 1);
            asm volatile("cp.async.wait_group 1;" ::: "memory");
        } else {
            asm volatile("cp.async.wait_group 0;" ::: "memory");
        }
        __syncthreads();                      // chunk c visible (also covers w1s/ams on c==0)
        if (tid < 220) {
            const float* xs = xbuf + (c & 1) * XBS;
            const float* wb = w1s + (c * CHUNK) * 24 + c0;
#pragma unroll
            for (int il = 0; il < CHUNK; il++) {
                u64 s = splat2(xs[il * 112 + n]);
                const u64* w = (const u64*)(wb + il * 24);
                acc[0] = ffma2(s, w[0], acc[0]); acc[1] = ffma2(s, w[1], acc[1]);
                acc[2] = ffma2(s, w[2], acc[2]); acc[3] = ffma2(s, w[3], acc[3]);
                acc[4] = ffma2(s, w[4], acc[4]); acc[5] = ffma2(s, w[5], acc[5]);
            }
        }
        __syncthreads();                      // reads of buf[c&1] done before it is reloaded
    }

    // --- epilogue of stage A: store feats half-row + partial logits ---
    if (tid < 220) {
        u64* fr = (u64*)(fs + n * 26 + c0);
#pragma unroll
        for (int j = 0; j < 6; j++) fr[j] = acc[j];
        const u64* ap = (const u64*)(as1 + h * 24 + c0);
        const u64* np = (const u64*)(an1 + h * 24 + c0);
        u64 sa = 0ull, sb = 0ull;
#pragma unroll
        for (int j = 0; j < 6; j++) {
            sa = ffma2(acc[j], ap[j], sa);
            sb = ffma2(acc[j], np[j], sb);
        }
        float2 fa = unpack2(sa), fb = unpack2(sb);
        pes[tid] = fa.x + fa.y;
        pen[tid] = fb.x + fb.y;
    }
    __syncthreads();
    if (tid < NN) {
        ess[tid] = pes[tid] + pes[tid + NN];
        ens[tid] = pen[tid] + pen[tid + NN];
    }
    __syncthreads();

    // --- stage B: sparse softmax + half-aggregation (R15 verbatim) ---
    if (tid < 220) {
        const float es = ess[n];
        u64 agg[6];
#pragma unroll
        for (int j = 0; j < 6; j++) agg[j] = 0ull;
        float sum = 0.f;
#pragma unroll
        for (int k = 0; k < 4; k++) {
            unsigned mw = ams[n * 4 + k];
            while (mw) {
                const int m2 = __ffs(mw) - 1;
                mw &= (mw - 1);
                const int m = k * 32 + m2;
                float v = es + ens[m];
                v = v > 0.f ? v : ALPHA * v;
                const float e = __expf(v);
                sum += e;
                const u64 s = splat2(e);
                const u64* w = (const u64*)(fs + m * 26 + c0);
                agg[0] = ffma2(s, w[0], agg[0]); agg[1] = ffma2(s, w[1], agg[1]);
                agg[2] = ffma2(s, w[2], agg[2]); agg[3] = ffma2(s, w[3], agg[3]);
                agg[4] = ffma2(s, w[4], agg[4]); agg[5] = ffma2(s, w[5], agg[5]);
            }
        }
        const float rinv = 1.f / sum;        // self-loop => sum > 0
        float* dst = g_h1T + (size_t)b * 13200 + (h * 24 + c0) * NN + n;
        const float* bb = b1 + c0;           // b1 shape [24], shared across heads
#pragma unroll
        for (int j = 0; j < 6; j++) {
            float2 p = unpack2(agg[j]);
            dst[(2 * j) * NN]     = lrelu(fmaf(p.x, rinv, bb[2 * j]));
            dst[(2 * j + 1) * NN] = lrelu(fmaf(p.y, rinv, bb[2 * j + 1]));
        }
    }
}

// ====== K3: layer-2, 384 threads, head-split (R15 verbatim) ======
__global__ __launch_bounds__(384, 4)
void k_layer2(const float* __restrict__ W2, const float* __restrict__ as2,
              const float* __restrict__ an2, const float* __restrict__ b2,
              const float* __restrict__ fc1, const float* __restrict__ fc2,
              float* __restrict__ out)
{
    __shared__ float w2s[1080];
    __shared__ float a2s[9], n2s[9];
    __shared__ __align__(16) float f2sl[1320];
    __shared__ __align__(16) float hps[1320];
    __shared__ float ess2[336], ens2[336];
    __shared__ unsigned ams[440];
    __shared__ float tss[112], uss[112];
    const int b = blockIdx.x, tid = threadIdx.x, lane = tid & 31, wid = tid >> 5;

    for (int idx = tid; idx < 1080; idx += 384) w2s[idx] = W2[idx];
    if (tid < 9) { a2s[tid] = as2[tid]; n2s[tid] = an2[tid]; }
    for (int idx = tid; idx < 440; idx += 384) ams[idx] = g_am[b * 440 + idx];
    __syncthreads();

    const int h2 = tid / NN;
    const int n = tid - h2 * NN;

    if (tid < 330) {
        float a0 = 0.f, a1 = 0.f, a2v = 0.f;
        const float* xp = g_h1T + (size_t)b * 13200 + n;
        const float* wp = w2s + h2 * 360;
#pragma unroll 8
        for (int k = 0; k < 120; k++) {
            float xv = xp[k * NN];
            a0 = fmaf(xv, wp[k * 3 + 0], a0);
            a1 = fmaf(xv, wp[k * 3 + 1], a1);
            a2v = fmaf(xv, wp[k * 3 + 2], a2v);
        }
        float e_s = a0 * a2s[h2 * 3] + a1 * a2s[h2 * 3 + 1] + a2v * a2s[h2 * 3 + 2];
        float e_n = a0 * n2s[h2 * 3] + a1 * n2s[h2 * 3 + 1] + a2v * n2s[h2 * 3 + 2];
        ess2[h2 * 112 + n] = e_s;
        ens2[h2 * 112 + n] = e_n;
        float4 o; o.x = a0; o.y = a1; o.z = a2v; o.w = 0.f;
        *(float4*)(f2sl + (h2 * NN + n) * 4) = o;
    }
    __syncthreads();

    if (tid < 330) {
        const float es = ess2[h2 * 112 + n];
        const float* ens = ens2 + h2 * 112;
        const ulonglong2* fbw = (const ulonglong2*)(f2sl + h2 * 440);
        u64 a0 = 0ull, a1 = 0ull;
        float sum = 0.f;
#pragma unroll
        for (int k = 0; k < 4; k++) {
            unsigned mw = ams[n * 4 + k];
            while (mw) {
                const int m2 = __ffs(mw) - 1;
                mw &= (mw - 1);
                const int m = k * 32 + m2;
                float v = es + ens[m];
                v = v > 0.f ? v : ALPHA * v;
                const float e = __expf(v);
                sum += e;
                const u64 s = splat2(e);
                ulonglong2 w = fbw[m];
                a0 = ffma2(s, w.x, a0);
                a1 = ffma2(s, w.y, a1);
            }
        }
        const float rinv = 1.f / sum;
        float2 v0 = unpack2(a0), v1 = unpack2(a1);
        float4 o; o.x = v0.x * rinv; o.y = v0.y * rinv; o.z = v1.x * rinv; o.w = 0.f;
        *(float4*)(hps + (h2 * NN + n) * 4) = o;
    }
    __syncthreads();

    if (tid < NN) {
        float4 p0 = *(const float4*)(hps + tid * 4);
        float4 p1 = *(const float4*)(hps + (NN + tid) * 4);
        float4 p2 = *(const float4*)(hps + (2 * NN + tid) * 4);
        float z = lrelu(fmaf((p0.x + p1.x + p2.x), (1.f / 3.f), b2[0])) * fc1[0]
                + lrelu(fmaf((p0.y + p1.y + p2.y), (1.f / 3.f), b2[1])) * fc1[1]
                + lrelu(fmaf((p0.z + p1.z + p2.z), (1.f / 3.f), b2[2])) * fc1[2];
        tss[tid] = sigm(z);
    }
    __syncthreads();

    if (tid < NN) uss[tid] = 0.f;
    __syncthreads();
    if (tid < 330) {
        int n0 = h2 * 37, n1 = n0 + 37 < NN ? n0 + 37 : NN;
        float s = 0.f;
        for (int n2 = n0; n2 < n1; n2++) s = fmaf(tss[n2], fc2[n2 * NN + n], s);
        atomicAdd(&uss[n], s);
    }
    __syncthreads();
    if (wid == 0) {
        float vmax = -3.4e38f;
        for (int m = lane; m < NN; m += 32) vmax = fmaxf(vmax, uss[m]);
        vmax = warp_max(vmax);
        float num = 0.f, den = 0.f;
        for (int m = lane; m < NN; m += 32) {
            float e = __expf(uss[m] - vmax);
            num = fmaf(tss[m], e, num);
            den += e;
        }
        num = warp_sum(num);
        den = warp_sum(den);
        if (lane == 0) out[b] = num / den;
    }
}

extern "C" void kernel_launch(void* const* d_in, const int* in_sizes, int n_in,
                              void* d_out, int out_size)
{
    const float* X   = (const float*)d_in[0];
    const float* A   = (const float*)d_in[1];
    const float* M   = (const float*)d_in[2];
    const float* W1  = (const float*)d_in[3];
    const float* as1 = (const float*)d_in[4];
    const float* an1 = (const float*)d_in[5];
    const float* b1  = (const float*)d_in[6];
    const float* W2  = (const float*)d_in[7];
    const float* as2 = (const float*)d_in[8];
    const float* an2 = (const float*)d_in[9];
    const float* b2  = (const float*)d_in[10];
    const float* fc1 = (const float*)d_in[11];
    const float* fc2 = (const float*)d_in[12];
    float* out = (float*)d_out;

    const int B = in_sizes[0] / (NN * NN);

    k_sigm<<<48, 256>>>(M);
    k_prep<<<B, 512>>>(X, A);
    k_layer1<<<dim3(5, B), 256>>>(W1, as1, an1, b1);
    k_layer2<<<B, 384>>>(W2, as2, an2, b2, fc1, fc2, out);
}

// round 17
// speedup vs baseline: 1.0789x; 1.0789x over previous
#include <cuda_runtime.h>
#include <math.h>

#define NN 110
#define ALPHA 0.2f

typedef unsigned long long u64;

__device__ __forceinline__ u64 ffma2(u64 a, u64 b, u64 c) {
    u64 d; asm("fma.rn.f32x2 %0, %1, %2, %3;" : "=l"(d) : "l"(a), "l"(b), "l"(c)); return d;
}
__device__ __forceinline__ u64 splat2(float x) {
    u64 d; asm("mov.b64 %0, {%1, %1};" : "=l"(d) : "f"(x)); return d;
}
__device__ __forceinline__ float2 unpack2(u64 v) {
    float2 r; asm("mov.b64 {%0, %1}, %2;" : "=f"(r.x), "=f"(r.y) : "l"(v)); return r;
}
__device__ __forceinline__ float lrelu(float v) { return v > 0.f ? v : ALPHA * v; }
__device__ __forceinline__ float sigm(float v) { return 1.f / (1.f + __expf(-v)); }
__device__ __forceinline__ float warp_sum(float v) {
#pragma unroll
    for (int o = 16; o > 0; o >>= 1) v += __shfl_xor_sync(0xffffffffu, v, o);
    return v;
}
__device__ __forceinline__ float warp_max(float v) {
#pragma unroll
    for (int o = 16; o > 0; o >>= 1) v = fmaxf(v, __shfl_xor_sync(0xffffffffu, v, o));
    return v;
}

// ---- global scratch ----
#define BMAX 2048
__device__ float    g_sigM[12100];                 // sigmoid(M), batch-invariant
__device__ float    g_xmT[(size_t)BMAX * 12320];   // [b][i4][n][4]  (i padded to 112)
__device__ float    g_h1T[(size_t)BMAX * 13200];   // [b][k=h*24+f][n]
__device__ unsigned g_am[BMAX * 440];              // [b][n][4]

// ================= K0: sigmoid(M) once =================
__global__ __launch_bounds__(256)
void k_sigm(const float* __restrict__ M)
{
    int idx = blockIdx.x * 256 + threadIdx.x;
    if (idx < 12100) g_sigM[idx] = sigm(M[idx]);
}

// ================= K1: Xm blocked transpose + adjacency masks =================
__global__ __launch_bounds__(512)
void k_prep(const float* __restrict__ X, const float* __restrict__ A)
{
    __shared__ __align__(16) float tile[110 * 111];   // [i][n]
    const int b = blockIdx.x, tid = threadIdx.x, lane = tid & 31, wid = tid >> 5;
    const float* Xb = X + (size_t)b * 12100;
    const float* Ab = A + (size_t)b * 12100;

    {
        const float4* x4 = (const float4*)Xb;
        const float4* m4 = (const float4*)g_sigM;
        for (int q = tid; q < 3025; q += 512) {
            float4 xv = x4[q];
            float4 mv = m4[q];
            int idx = q * 4;
            int n = idx / NN, i = idx - n * NN;
            float vals[4] = { xv.x * mv.x, xv.y * mv.y, xv.z * mv.z, xv.w * mv.w };
#pragma unroll
            for (int j = 0; j < 4; j++) {
                tile[i * 111 + n] = vals[j];
                if (++i == NN) { i = 0; n++; }
            }
        }
    }
    for (int w = wid; w < 440; w += 16) {
        int n = w >> 2, seg = w & 3;
        int m = seg * 32 + lane;
        float a = (m < NN) ? Ab[n * NN + m] : 0.f;
        unsigned bal = __ballot_sync(0xffffffffu, a > 0.f);
        if (lane == 0) g_am[b * 440 + w] = bal;
    }
    __syncthreads();
    // blocked write-out: d4[i4*110+n] = (Xm[n][4i4..4i4+3]), zeros for i >= 110
    {
        float4* d4 = (float4*)(g_xmT + (size_t)b * 12320);
        for (int q = tid; q < 3080; q += 512) {
            int i4 = q / NN, n = q - i4 * NN;
            int i0 = i4 * 4;
            float4 o;
            o.x = tile[i0 * 111 + n];
            o.y = tile[(i0 + 1) * 111 + n];
            o.z = (i0 + 2 < NN) ? tile[(i0 + 2) * 111 + n] : 0.f;
            o.w = (i0 + 3 < NN) ? tile[(i0 + 3) * 111 + n] : 0.f;
            d4[q] = o;
        }
    }
}

// ====== K2: layer-1, 256 threads, column-halved, float4 K-blocked loads ======
__global__ __launch_bounds__(256, 5)
void k_layer1(const float* __restrict__ W1, const float* __restrict__ as1,
              const float* __restrict__ an1, const float* __restrict__ b1)
{
    __shared__ __align__(16) float w1s[2688];   // 112 rows x 24, rows 110-111 zero
    __shared__ __align__(16) float fs[110 * 26 + 4];
    __shared__ float pes[220], pen[220];
    __shared__ float ess[112], ens[112];
    __shared__ unsigned ams[440];
    const int h = blockIdx.x, b = blockIdx.y, tid = threadIdx.x;

    const float* wsrc = W1 + h * 2640;
    for (int idx = tid; idx < 2688; idx += 256) w1s[idx] = (idx < 2640) ? wsrc[idx] : 0.f;
    for (int idx = tid; idx < 440; idx += 256) ams[idx] = g_am[b * 440 + idx];
    __syncthreads();

    const int half = tid / NN;               // 0 or 1 for tid<220
    const int n = tid - half * NN;
    const int c0 = half * 12;

    // --- stage A: half-row GEMM, 4 K-steps per LDG.128 ---
    if (tid < 220) {
        const float4* xp4 = (const float4*)(g_xmT + (size_t)b * 12320);
        u64 acc[6];
#pragma unroll
        for (int j = 0; j < 6; j++) acc[j] = 0ull;
#pragma unroll 7
        for (int i4 = 0; i4 < 28; i4++) {
            float4 xv = xp4[i4 * NN + n];    // coalesced LDG.128
            const float* wb = w1s + (i4 * 4) * 24 + c0;
            float xs[4] = { xv.x, xv.y, xv.z, xv.w };
#pragma unroll
            for (int j2 = 0; j2 < 4; j2++) {
                u64 s = splat2(xs[j2]);
                const u64* w = (const u64*)(wb + j2 * 24);
                acc[0] = ffma2(s, w[0], acc[0]); acc[1] = ffma2(s, w[1], acc[1]);
                acc[2] = ffma2(s, w[2], acc[2]); acc[3] = ffma2(s, w[3], acc[3]);
                acc[4] = ffma2(s, w[4], acc[4]); acc[5] = ffma2(s, w[5], acc[5]);
            }
        }
        u64* fr = (u64*)(fs + n * 26 + c0);
#pragma unroll
        for (int j = 0; j < 6; j++) fr[j] = acc[j];
        const u64* ap = (const u64*)(as1 + h * 24 + c0);
        const u64* np = (const u64*)(an1 + h * 24 + c0);
        u64 sa = 0ull, sb = 0ull;
#pragma unroll
        for (int j = 0; j < 6; j++) {
            sa = ffma2(acc[j], ap[j], sa);
            sb = ffma2(acc[j], np[j], sb);
        }
        float2 fa = unpack2(sa), fb = unpack2(sb);
        pes[tid] = fa.x + fa.y;
        pen[tid] = fb.x + fb.y;
    }
    __syncthreads();
    if (tid < NN) {
        ess[tid] = pes[tid] + pes[tid + NN];
        ens[tid] = pen[tid] + pen[tid + NN];
    }
    __syncthreads();

    // --- stage B: sparse softmax + half-aggregation (R15 verbatim) ---
    if (tid < 220) {
        const float es = ess[n];
        u64 agg[6];
#pragma unroll
        for (int j = 0; j < 6; j++) agg[j] = 0ull;
        float sum = 0.f;
#pragma unroll
        for (int k = 0; k < 4; k++) {
            unsigned mw = ams[n * 4 + k];
            while (mw) {
                const int m2 = __ffs(mw) - 1;
                mw &= (mw - 1);
                const int m = k * 32 + m2;
                float v = es + ens[m];
                v = v > 0.f ? v : ALPHA * v;
                const float e = __expf(v);
                sum += e;
                const u64 s = splat2(e);
                const u64* w = (const u64*)(fs + m * 26 + c0);
                agg[0] = ffma2(s, w[0], agg[0]); agg[1] = ffma2(s, w[1], agg[1]);
                agg[2] = ffma2(s, w[2], agg[2]); agg[3] = ffma2(s, w[3], agg[3]);
                agg[4] = ffma2(s, w[4], agg[4]); agg[5] = ffma2(s, w[5], agg[5]);
            }
        }
        const float rinv = 1.f / sum;        // self-loop => sum > 0
        float* dst = g_h1T + (size_t)b * 13200 + (h * 24 + c0) * NN + n;
        const float* bb = b1 + c0;           // b1 shape [24], shared across heads
#pragma unroll
        for (int j = 0; j < 6; j++) {
            float2 p = unpack2(agg[j]);
            dst[(2 * j) * NN]     = lrelu(fmaf(p.x, rinv, bb[2 * j]));
            dst[(2 * j + 1) * NN] = lrelu(fmaf(p.y, rinv, bb[2 * j + 1]));
        }
    }
}

// ====== K3: layer-2, 384 threads, head-split (R15 verbatim) ======
__global__ __launch_bounds__(384, 4)
void k_layer2(const float* __restrict__ W2, const float* __restrict__ as2,
              const float* __restrict__ an2, const float* __restrict__ b2,
              const float* __restrict__ fc1, const float* __restrict__ fc2,
              float* __restrict__ out)
{
    __shared__ float w2s[1080];
    __shared__ float a2s[9], n2s[9];
    __shared__ __align__(16) float f2sl[1320];
    __shared__ __align__(16) float hps[1320];
    __shared__ float ess2[336], ens2[336];
    __shared__ unsigned ams[440];
    __shared__ float tss[112], uss[112];
    const int b = blockIdx.x, tid = threadIdx.x, lane = tid & 31, wid = tid >> 5;

    for (int idx = tid; idx < 1080; idx += 384) w2s[idx] = W2[idx];
    if (tid < 9) { a2s[tid] = as2[tid]; n2s[tid] = an2[tid]; }
    for (int idx = tid; idx < 440; idx += 384) ams[idx] = g_am[b * 440 + idx];
    __syncthreads();

    const int h2 = tid / NN;
    const int n = tid - h2 * NN;

    if (tid < 330) {
        float a0 = 0.f, a1 = 0.f, a2v = 0.f;
        const float* xp = g_h1T + (size_t)b * 13200 + n;
        const float* wp = w2s + h2 * 360;
#pragma unroll 8
        for (int k = 0; k < 120; k++) {
            float xv = xp[k * NN];
            a0 = fmaf(xv, wp[k * 3 + 0], a0);
            a1 = fmaf(xv, wp[k * 3 + 1], a1);
            a2v = fmaf(xv, wp[k * 3 + 2], a2v);
        }
        float e_s = a0 * a2s[h2 * 3] + a1 * a2s[h2 * 3 + 1] + a2v * a2s[h2 * 3 + 2];
        float e_n = a0 * n2s[h2 * 3] + a1 * n2s[h2 * 3 + 1] + a2v * n2s[h2 * 3 + 2];
        ess2[h2 * 112 + n] = e_s;
        ens2[h2 * 112 + n] = e_n;
        float4 o; o.x = a0; o.y = a1; o.z = a2v; o.w = 0.f;
        *(float4*)(f2sl + (h2 * NN + n) * 4) = o;
    }
    __syncthreads();

    if (tid < 330) {
        const float es = ess2[h2 * 112 + n];
        const float* ens = ens2 + h2 * 112;
        const ulonglong2* fbw = (const ulonglong2*)(f2sl + h2 * 440);
        u64 a0 = 0ull, a1 = 0ull;
        float sum = 0.f;
#pragma unroll
        for (int k = 0; k < 4; k++) {
            unsigned mw = ams[n * 4 + k];
            while (mw) {
                const int m2 = __ffs(mw) - 1;
                mw &= (mw - 1);
                const int m = k * 32 + m2;
                float v = es + ens[m];
                v = v > 0.f ? v : ALPHA * v;
                const float e = __expf(v);
                sum += e;
                const u64 s = splat2(e);
                ulonglong2 w = fbw[m];
                a0 = ffma2(s, w.x, a0);
                a1 = ffma2(s, w.y, a1);
            }
        }
        const float rinv = 1.f / sum;
        float2 v0 = unpack2(a0), v1 = unpack2(a1);
        float4 o; o.x = v0.x * rinv; o.y = v0.y * rinv; o.z = v1.x * rinv; o.w = 0.f;
        *(float4*)(hps + (h2 * NN + n) * 4) = o;
    }
    __syncthreads();

    if (tid < NN) {
        float4 p0 = *(const float4*)(hps + tid * 4);
        float4 p1 = *(const float4*)(hps + (NN + tid) * 4);
        float4 p2 = *(const float4*)(hps + (2 * NN + tid) * 4);
        float z = lrelu(fmaf((p0.x + p1.x + p2.x), (1.f / 3.f), b2[0])) * fc1[0]
                + lrelu(fmaf((p0.y + p1.y + p2.y), (1.f / 3.f), b2[1])) * fc1[1]
                + lrelu(fmaf((p0.z + p1.z + p2.z), (1.f / 3.f), b2[2])) * fc1[2];
        tss[tid] = sigm(z);
    }
    __syncthreads();

    if (tid < NN) uss[tid] = 0.f;
    __syncthreads();
    if (tid < 330) {
        int n0 = h2 * 37, n1 = n0 + 37 < NN ? n0 + 37 : NN;
        float s = 0.f;
        for (int n2 = n0; n2 < n1; n2++) s = fmaf(tss[n2], fc2[n2 * NN + n], s);
        atomicAdd(&uss[n], s);
    }
    __syncthreads();
    if (wid == 0) {
        float vmax = -3.4e38f;
        for (int m = lane; m < NN; m += 32) vmax = fmaxf(vmax, uss[m]);
        vmax = warp_max(vmax);
        float num = 0.f, den = 0.f;
        for (int m = lane; m < NN; m += 32) {
            float e = __expf(uss[m] - vmax);
            num = fmaf(tss[m], e, num);
            den += e;
        }
        num = warp_sum(num);
        den = warp_sum(den);
        if (lane == 0) out[b] = num / den;
    }
}

extern "C" void kernel_launch(void* const* d_in, const int* in_sizes, int n_in,
                              void* d_out, int out_size)
{
    const float* X   = (const float*)d_in[0];
    const float* A   = (const float*)d_in[1];
    const float* M   = (const float*)d_in[2];
    const float* W1  = (const float*)d_in[3];
    const float* as1 = (const float*)d_in[4];
    const float* an1 = (const float*)d_in[5];
    const float* b1  = (const float*)d_in[6];
    const float* W2  = (const float*)d_in[7];
    const float* as2 = (const float*)d_in[8];
    const float* an2 = (const float*)d_in[9];
    const float* b2  = (const float*)d_in[10];
    const float* fc1 = (const float*)d_in[11];
    const float* fc2 = (const float*)d_in[12];
    float* out = (float*)d_out;

    const int B = in_sizes[0] / (NN * NN);

    k_sigm<<<48, 256>>>(M);
    k_prep<<<B, 512>>>(X, A);
    k_layer1<<<dim3(5, B), 256>>>(W1, as1, an1, b1);
    k_layer2<<<B, 384>>>(W2, as2, an2, b2, fc1, fc2, out);
}